// round 1
// baseline (speedup 1.0000x reference)
#include <cuda_runtime.h>

#define SEQ   4096
#define HID   1024
#define INTER 4096
#define NH    16
#define HD    64

// ---------------- device scratch (no allocations allowed) ----------------
__device__ float g_xn [SEQ * HID];
__device__ float g_q  [SEQ * HID];
__device__ float g_k  [SEQ * HID];
__device__ float g_v  [SEQ * HID];
__device__ float g_ctx[SEQ * HID];
__device__ float g_x1 [SEQ * HID];
__device__ float g_h  [SEQ * INTER];

// ---------------- mean-only layernorm: out = w*(x - mean(x)) + b ----------
__global__ __launch_bounds__(256) void ln_kernel(const float* __restrict__ x,
                                                 const float* __restrict__ w,
                                                 const float* __restrict__ b,
                                                 float* __restrict__ out) {
    int row = blockIdx.x;
    int tid = threadIdx.x;
    const float4* xr = reinterpret_cast<const float4*>(x + (size_t)row * HID);
    float4 xv = xr[tid];                       // 256 threads * 4 = 1024
    float s = xv.x + xv.y + xv.z + xv.w;
    #pragma unroll
    for (int o = 16; o; o >>= 1) s += __shfl_xor_sync(0xffffffffu, s, o);
    __shared__ float red[8];
    if ((tid & 31) == 0) red[tid >> 5] = s;
    __syncthreads();
    if (tid < 8) {
        float t = red[tid];
        #pragma unroll
        for (int o = 4; o; o >>= 1) t += __shfl_xor_sync(0xffu, t, o);
        if (tid == 0) red[0] = t;
    }
    __syncthreads();
    float mean = red[0] * (1.0f / HID);
    float4 wv = reinterpret_cast<const float4*>(w)[tid];
    float4 bv = reinterpret_cast<const float4*>(b)[tid];
    float4 ov;
    ov.x = wv.x * (xv.x - mean) + bv.x;
    ov.y = wv.y * (xv.y - mean) + bv.y;
    ov.z = wv.z * (xv.z - mean) + bv.z;
    ov.w = wv.w * (xv.w - mean) + bv.w;
    reinterpret_cast<float4*>(out + (size_t)row * HID)[tid] = ov;
}

// ---------------- C[M,N] = A[M,K] @ B[N,K]^T + bias (+relu) (+res) --------
// 64x64 block tile, BK=16, 256 threads, 4x4 per-thread microtile.
template <bool RELU, bool RES>
__global__ __launch_bounds__(256) void gemm_kernel(const float* __restrict__ A,
                                                   const float* __restrict__ B,
                                                   const float* __restrict__ bias,
                                                   const float* __restrict__ res,
                                                   float* __restrict__ C,
                                                   int M, int N, int K) {
    __shared__ float As[64][17];
    __shared__ float Bs[64][17];
    int tid = threadIdx.x;
    int tx = tid & 15, ty = tid >> 4;
    int m0 = blockIdx.y * 64, n0 = blockIdx.x * 64;
    int lr = tid >> 2;            // 0..63 row within tile
    int lc = (tid & 3) << 2;      // 0,4,8,12 col within tile

    float acc[4][4] = {};

    for (int k0 = 0; k0 < K; k0 += 16) {
        float4 av = *reinterpret_cast<const float4*>(A + (size_t)(m0 + lr) * K + k0 + lc);
        float4 bv = *reinterpret_cast<const float4*>(B + (size_t)(n0 + lr) * K + k0 + lc);
        As[lr][lc + 0] = av.x; As[lr][lc + 1] = av.y;
        As[lr][lc + 2] = av.z; As[lr][lc + 3] = av.w;
        Bs[lr][lc + 0] = bv.x; Bs[lr][lc + 1] = bv.y;
        Bs[lr][lc + 2] = bv.z; Bs[lr][lc + 3] = bv.w;
        __syncthreads();
        #pragma unroll
        for (int k = 0; k < 16; k++) {
            float a[4], b[4];
            #pragma unroll
            for (int i = 0; i < 4; i++) a[i] = As[ty * 4 + i][k];
            #pragma unroll
            for (int j = 0; j < 4; j++) b[j] = Bs[tx * 4 + j][k];
            #pragma unroll
            for (int i = 0; i < 4; i++)
                #pragma unroll
                for (int j = 0; j < 4; j++)
                    acc[i][j] = fmaf(a[i], b[j], acc[i][j]);
        }
        __syncthreads();
    }

    #pragma unroll
    for (int i = 0; i < 4; i++) {
        int m = m0 + ty * 4 + i;
        #pragma unroll
        for (int j = 0; j < 4; j++) {
            int n = n0 + tx * 4 + j;
            float c = acc[i][j] + bias[n];
            if (RELU) c = fmaxf(c, 0.0f);
            if (RES)  c += res[(size_t)m * N + n];
            C[(size_t)m * N + n] = c;
        }
    }
}

// ---------------- flash attention: per (query-tile 64, head) --------------
// 256 threads; each thread owns a 4x4 patch of the 64x64 score tile
// (rows ty*4.., cols tx*4..) and a 4x4 patch of the O accumulator
// (rows ty*4.., dims tx*4..). Row stats replicated across the tx group.
__global__ __launch_bounds__(256) void flash_kernel(const float* __restrict__ Q,
                                                    const float* __restrict__ K,
                                                    const float* __restrict__ V,
                                                    float* __restrict__ O) {
    extern __shared__ float sm[];
    float (*Qs)[65] = reinterpret_cast<float(*)[65]>(sm);
    float (*Ks)[65] = reinterpret_cast<float(*)[65]>(sm + 64 * 65);
    float (*Vs)[65] = reinterpret_cast<float(*)[65]>(sm + 2 * 64 * 65);
    float (*Ps)[65] = reinterpret_cast<float(*)[65]>(sm + 3 * 64 * 65);

    int tid = threadIdx.x;
    int tx = tid & 15, ty = tid >> 4;
    int q0 = blockIdx.x * 64;
    int hc = blockIdx.y * HD;
    int r0 = ty * 4, c0 = tx * 4;

    // load Q tile, pre-scaled by 1/sqrt(64)
    for (int vix = tid; vix < 64 * 16; vix += 256) {
        int r = vix >> 4, c4 = (vix & 15) << 2;
        float4 qv = *reinterpret_cast<const float4*>(Q + (size_t)(q0 + r) * HID + hc + c4);
        Qs[r][c4 + 0] = qv.x * 0.125f; Qs[r][c4 + 1] = qv.y * 0.125f;
        Qs[r][c4 + 2] = qv.z * 0.125f; Qs[r][c4 + 3] = qv.w * 0.125f;
    }

    float mrow[4], lrow[4], o[4][4];
    #pragma unroll
    for (int i = 0; i < 4; i++) {
        mrow[i] = -1e30f; lrow[i] = 0.0f;
        #pragma unroll
        for (int d = 0; d < 4; d++) o[i][d] = 0.0f;
    }

    for (int kt = 0; kt < SEQ; kt += 64) {
        __syncthreads();   // previous PV done before overwriting K/V tiles
        for (int vix = tid; vix < 64 * 16; vix += 256) {
            int r = vix >> 4, c4 = (vix & 15) << 2;
            float4 kv = *reinterpret_cast<const float4*>(K + (size_t)(kt + r) * HID + hc + c4);
            float4 vv = *reinterpret_cast<const float4*>(V + (size_t)(kt + r) * HID + hc + c4);
            Ks[r][c4 + 0] = kv.x; Ks[r][c4 + 1] = kv.y;
            Ks[r][c4 + 2] = kv.z; Ks[r][c4 + 3] = kv.w;
            Vs[r][c4 + 0] = vv.x; Vs[r][c4 + 1] = vv.y;
            Vs[r][c4 + 2] = vv.z; Vs[r][c4 + 3] = vv.w;
        }
        __syncthreads();

        // S = Qs @ Ks^T (scale already folded into Q)
        float s[4][4] = {};
        #pragma unroll 8
        for (int k = 0; k < HD; k++) {
            float a[4], b[4];
            #pragma unroll
            for (int i = 0; i < 4; i++) a[i] = Qs[r0 + i][k];
            #pragma unroll
            for (int j = 0; j < 4; j++) b[j] = Ks[c0 + j][k];
            #pragma unroll
            for (int i = 0; i < 4; i++)
                #pragma unroll
                for (int j = 0; j < 4; j++)
                    s[i][j] = fmaf(a[i], b[j], s[i][j]);
        }

        // online softmax per row (replicated across the 16-lane tx group)
        #pragma unroll
        for (int i = 0; i < 4; i++) {
            float rm = fmaxf(fmaxf(s[i][0], s[i][1]), fmaxf(s[i][2], s[i][3]));
            rm = fmaxf(rm, __shfl_xor_sync(0xffffffffu, rm, 1));
            rm = fmaxf(rm, __shfl_xor_sync(0xffffffffu, rm, 2));
            rm = fmaxf(rm, __shfl_xor_sync(0xffffffffu, rm, 4));
            rm = fmaxf(rm, __shfl_xor_sync(0xffffffffu, rm, 8));
            float mn = fmaxf(mrow[i], rm);
            float alpha = __expf(mrow[i] - mn);
            mrow[i] = mn;
            float rs = 0.0f;
            #pragma unroll
            for (int j = 0; j < 4; j++) {
                float p = __expf(s[i][j] - mn);
                s[i][j] = p;
                rs += p;
            }
            rs += __shfl_xor_sync(0xffffffffu, rs, 1);
            rs += __shfl_xor_sync(0xffffffffu, rs, 2);
            rs += __shfl_xor_sync(0xffffffffu, rs, 4);
            rs += __shfl_xor_sync(0xffffffffu, rs, 8);
            lrow[i] = lrow[i] * alpha + rs;
            #pragma unroll
            for (int d = 0; d < 4; d++) o[i][d] *= alpha;
            #pragma unroll
            for (int j = 0; j < 4; j++) Ps[r0 + i][c0 + j] = s[i][j];
        }
        __syncthreads();

        // O += P @ V
        #pragma unroll 8
        for (int j = 0; j < 64; j++) {
            float p[4], v[4];
            #pragma unroll
            for (int i = 0; i < 4; i++) p[i] = Ps[r0 + i][j];
            #pragma unroll
            for (int d = 0; d < 4; d++) v[d] = Vs[j][c0 + d];
            #pragma unroll
            for (int i = 0; i < 4; i++)
                #pragma unroll
                for (int d = 0; d < 4; d++)
                    o[i][d] = fmaf(p[i], v[d], o[i][d]);
        }
    }

    #pragma unroll
    for (int i = 0; i < 4; i++) {
        float inv = 1.0f / lrow[i];
        #pragma unroll
        for (int d = 0; d < 4; d++)
            O[(size_t)(q0 + r0 + i) * HID + hc + c0 + d] = o[i][d] * inv;
    }
}

// ---------------- launch --------------------------------------------------
extern "C" void kernel_launch(void* const* d_in, const int* in_sizes, int n_in,
                              void* d_out, int out_size) {
    const float* x     = (const float*)d_in[0];
    const float* an_w  = (const float*)d_in[1];
    const float* an_b  = (const float*)d_in[2];
    const float* q_w   = (const float*)d_in[3];
    const float* q_b   = (const float*)d_in[4];
    const float* k_w   = (const float*)d_in[5];
    const float* k_b   = (const float*)d_in[6];
    const float* v_w   = (const float*)d_in[7];
    const float* v_b   = (const float*)d_in[8];
    const float* o_w   = (const float*)d_in[9];
    const float* o_b   = (const float*)d_in[10];
    const float* fn_w  = (const float*)d_in[11];
    const float* fn_b  = (const float*)d_in[12];
    const float* ff1_w = (const float*)d_in[13];
    const float* ff1_b = (const float*)d_in[14];
    const float* ff2_w = (const float*)d_in[15];
    const float* ff2_b = (const float*)d_in[16];
    float* out = (float*)d_out;

    float *xn, *q, *k, *v, *ctx, *x1, *hbuf;
    cudaGetSymbolAddress((void**)&xn,   g_xn);
    cudaGetSymbolAddress((void**)&q,    g_q);
    cudaGetSymbolAddress((void**)&k,    g_k);
    cudaGetSymbolAddress((void**)&v,    g_v);
    cudaGetSymbolAddress((void**)&ctx,  g_ctx);
    cudaGetSymbolAddress((void**)&x1,   g_x1);
    cudaGetSymbolAddress((void**)&hbuf, g_h);

    const int FLASH_SMEM = 4 * 64 * 65 * sizeof(float);   // 66560 B
    cudaFuncSetAttribute(flash_kernel, cudaFuncAttributeMaxDynamicSharedMemorySize,
                         FLASH_SMEM);

    dim3 g_proj(HID / 64, SEQ / 64);     // (16, 64)
    dim3 g_ff1 (INTER / 64, SEQ / 64);   // (64, 64)

    // xn = LN(x)
    ln_kernel<<<SEQ, 256>>>(x, an_w, an_b, xn);
    // Q/K/V projections
    gemm_kernel<false, false><<<g_proj, 256>>>(xn, q_w, q_b, nullptr, q, SEQ, HID, HID);
    gemm_kernel<false, false><<<g_proj, 256>>>(xn, k_w, k_b, nullptr, k, SEQ, HID, HID);
    gemm_kernel<false, false><<<g_proj, 256>>>(xn, v_w, v_b, nullptr, v, SEQ, HID, HID);
    // attention
    flash_kernel<<<dim3(SEQ / 64, NH), 256, FLASH_SMEM>>>(q, k, v, ctx);
    // x1 = ctx @ o_w^T + o_b + x
    gemm_kernel<false, true><<<g_proj, 256>>>(ctx, o_w, o_b, x, x1, SEQ, HID, HID);
    // xn = LN(x1)
    ln_kernel<<<SEQ, 256>>>(x1, fn_w, fn_b, xn);
    // h = relu(xn @ ff1_w^T + ff1_b)
    gemm_kernel<true, false><<<g_ff1, 256>>>(xn, ff1_w, ff1_b, nullptr, hbuf, SEQ, INTER, HID);
    // out = h @ ff2_w^T + ff2_b + x1
    gemm_kernel<false, true><<<g_proj, 256>>>(hbuf, ff2_w, ff2_b, x1, out, SEQ, HID, INTER);
}

// round 3
// speedup vs baseline: 4.6269x; 4.6269x over previous
#include <cuda_runtime.h>
#include <cuda_bf16.h>
#include <cstdint>

#define SEQ   4096
#define HID   1024
#define INTER 4096
#define NH    16
#define HD    64

// ---------------- device scratch (no allocations allowed) ----------------
__device__ float          g_xn [SEQ * HID];
__device__ __nv_bfloat16  g_qb [SEQ * HID];
__device__ __nv_bfloat16  g_kb [SEQ * HID];
__device__ __nv_bfloat16  g_vb [SEQ * HID];
__device__ float          g_ctx[SEQ * HID];
__device__ float          g_x1 [SEQ * HID];
__device__ float          g_h  [SEQ * INTER];

// ======================= low-level helpers ================================
__device__ __forceinline__ uint32_t smem_u32(const void* p) {
    uint32_t a;
    asm("{ .reg .u64 t; cvta.to.shared.u64 t, %1; cvt.u32.u64 %0, t; }"
        : "=r"(a) : "l"(p));
    return a;
}
// pack two fp32 -> bf16x2 (lo in lower half, hi in upper half)
__device__ __forceinline__ uint32_t pack_bf16(float lo, float hi) {
    uint32_t r;
    asm("cvt.rn.satfinite.bf16x2.f32 %0, %1, %2;" : "=r"(r) : "f"(hi), "f"(lo));
    return r;
}
__device__ __forceinline__ void ldsm4(uint32_t* r, uint32_t addr) {
    asm volatile("ldmatrix.sync.aligned.m8n8.x4.shared.b16 {%0,%1,%2,%3}, [%4];"
        : "=r"(r[0]), "=r"(r[1]), "=r"(r[2]), "=r"(r[3]) : "r"(addr));
}
__device__ __forceinline__ void ldsm4t(uint32_t* r, uint32_t addr) {
    asm volatile("ldmatrix.sync.aligned.m8n8.x4.trans.shared.b16 {%0,%1,%2,%3}, [%4];"
        : "=r"(r[0]), "=r"(r[1]), "=r"(r[2]), "=r"(r[3]) : "r"(addr));
}
__device__ __forceinline__ void mma16816(float* d, const uint32_t* a,
                                         const uint32_t* b, const float* c) {
    asm volatile(
        "mma.sync.aligned.m16n8k16.row.col.f32.bf16.bf16.f32 "
        "{%0,%1,%2,%3}, {%4,%5,%6,%7}, {%8,%9}, {%10,%11,%12,%13};"
        : "=f"(d[0]), "=f"(d[1]), "=f"(d[2]), "=f"(d[3])
        : "r"(a[0]), "r"(a[1]), "r"(a[2]), "r"(a[3]),
          "r"(b[0]), "r"(b[1]),
          "f"(c[0]), "f"(c[1]), "f"(c[2]), "f"(c[3]));
}
// split fp32x4 into bf16 hi + residual lo, packed as uint2 each
__device__ __forceinline__ void split4(float4 a, uint2& hi, uint2& lo) {
    uint32_t h01 = pack_bf16(a.x, a.y);
    uint32_t h23 = pack_bf16(a.z, a.w);
    float hx = __uint_as_float(h01 << 16);
    float hy = __uint_as_float(h01 & 0xffff0000u);
    float hz = __uint_as_float(h23 << 16);
    float hw = __uint_as_float(h23 & 0xffff0000u);
    uint32_t l01 = pack_bf16(a.x - hx, a.y - hy);
    uint32_t l23 = pack_bf16(a.z - hz, a.w - hw);
    hi = make_uint2(h01, h23);
    lo = make_uint2(l01, l23);
}

// ---------------- mean-only layernorm: out = w*(x - mean(x)) + b ----------
__global__ __launch_bounds__(256) void ln_kernel(const float* __restrict__ x,
                                                 const float* __restrict__ w,
                                                 const float* __restrict__ b,
                                                 float* __restrict__ out) {
    int row = blockIdx.x;
    int tid = threadIdx.x;
    const float4* xr = reinterpret_cast<const float4*>(x + (size_t)row * HID);
    float4 xv = xr[tid];
    float s = xv.x + xv.y + xv.z + xv.w;
    #pragma unroll
    for (int o = 16; o; o >>= 1) s += __shfl_xor_sync(0xffffffffu, s, o);
    __shared__ float red[8];
    if ((tid & 31) == 0) red[tid >> 5] = s;
    __syncthreads();
    if (tid < 8) {
        float t = red[tid];
        #pragma unroll
        for (int o = 4; o; o >>= 1) t += __shfl_xor_sync(0xffu, t, o);
        if (tid == 0) red[0] = t;
    }
    __syncthreads();
    float mean = red[0] * (1.0f / HID);
    float4 wv = reinterpret_cast<const float4*>(w)[tid];
    float4 bv = reinterpret_cast<const float4*>(b)[tid];
    float4 ov;
    ov.x = wv.x * (xv.x - mean) + bv.x;
    ov.y = wv.y * (xv.y - mean) + bv.y;
    ov.z = wv.z * (xv.z - mean) + bv.z;
    ov.w = wv.w * (xv.w - mean) + bv.w;
    reinterpret_cast<float4*>(out + (size_t)row * HID)[tid] = ov;
}

// ====================== HMMA split-bf16 GEMM ==============================
// C[M,N] = A[M,K] @ B[N,K]^T + bias (+relu) (+res); optional bf16 output.
// CTA tile 128x128, k-chunk 16 fp32, double-buffered smem.
// fp32 emulation: D = Ah*Bh + Ah*Bl + Al*Bh (fp32 accumulators).
#define TILE_BYTES 6144          // 128 rows * 24 bf16 * 2B (stride 24 = pad)
#define BOFF       24576         // B tiles start after 4 A tiles
#define GSMEM      49152

template <int RELU, int RES, int OBF16>
__global__ __launch_bounds__(256, 2) void hgemm(const float* __restrict__ A,
                                                const float* __restrict__ B,
                                                const float* __restrict__ bias,
                                                const float* __restrict__ res,
                                                void* __restrict__ Cout,
                                                int M, int N, int K) {
    extern __shared__ __align__(16) char sm[];
    const uint32_t sb = smem_u32(sm);
    const int tid = threadIdx.x, lane = tid & 31, wid = tid >> 5;
    const int wm = (wid >> 2) << 6;       // 0 or 64
    const int wn = (wid & 3) << 5;        // 0,32,64,96
    const int m0 = blockIdx.y << 7, n0 = blockIdx.x << 7;
    const int r_ = tid >> 2, c4 = (tid & 3) << 2;

    const int aoff = (lane & 15) * 48 + (lane >> 4) * 16;
    const int boff = ((lane & 7) + ((lane >> 4) << 3)) * 48 + ((lane & 8) << 1);
    const int soff = r_ * 48 + c4 * 2;

    float acc[4][4][4] = {};

    const float* Aptr = A + (size_t)(m0 + r_) * K + c4;
    const float* Bptr = B + (size_t)(n0 + r_) * K + c4;
    const int NC = K >> 4;

    float4 a0 = *(const float4*)(Aptr);
    float4 a1 = *(const float4*)(Aptr + (size_t)64 * K);
    float4 b0 = *(const float4*)(Bptr);
    float4 b1 = *(const float4*)(Bptr + (size_t)64 * K);

    // STS stage 0
    {
        uint2 h, l;
        split4(a0, h, l);
        *(uint2*)(sm + 0 * TILE_BYTES + soff) = h;
        *(uint2*)(sm + 1 * TILE_BYTES + soff) = l;
        split4(a1, h, l);
        *(uint2*)(sm + 0 * TILE_BYTES + soff + 64 * 48) = h;
        *(uint2*)(sm + 1 * TILE_BYTES + soff + 64 * 48) = l;
        split4(b0, h, l);
        *(uint2*)(sm + BOFF + 0 * TILE_BYTES + soff) = h;
        *(uint2*)(sm + BOFF + 1 * TILE_BYTES + soff) = l;
        split4(b1, h, l);
        *(uint2*)(sm + BOFF + 0 * TILE_BYTES + soff + 64 * 48) = h;
        *(uint2*)(sm + BOFF + 1 * TILE_BYTES + soff + 64 * 48) = l;
    }
    __syncthreads();

    for (int kc = 0; kc < NC; kc++) {
        const int st = kc & 1;
        const int sta = (st << 1) * TILE_BYTES;          // A hi
        if (kc + 1 < NC) {
            const float* Ap = Aptr + (kc + 1) * 16;
            const float* Bp = Bptr + (kc + 1) * 16;
            a0 = *(const float4*)(Ap);
            a1 = *(const float4*)(Ap + (size_t)64 * K);
            b0 = *(const float4*)(Bp);
            b1 = *(const float4*)(Bp + (size_t)64 * K);
        }

        uint32_t bh[8], bl[8];
        ldsm4(bh + 0, sb + BOFF + sta + (wn +  0) * 48 + boff);
        ldsm4(bh + 4, sb + BOFF + sta + (wn + 16) * 48 + boff);
        ldsm4(bl + 0, sb + BOFF + sta + TILE_BYTES + (wn +  0) * 48 + boff);
        ldsm4(bl + 4, sb + BOFF + sta + TILE_BYTES + (wn + 16) * 48 + boff);

        #pragma unroll
        for (int i = 0; i < 4; i++) {
            uint32_t ah[4];
            ldsm4(ah, sb + sta + (wm + 16 * i) * 48 + aoff);
            #pragma unroll
            for (int j = 0; j < 4; j++) mma16816(acc[i][j], ah, bh + 2 * j, acc[i][j]);
            #pragma unroll
            for (int j = 0; j < 4; j++) mma16816(acc[i][j], ah, bl + 2 * j, acc[i][j]);
        }
        #pragma unroll
        for (int i = 0; i < 4; i++) {
            uint32_t al[4];
            ldsm4(al, sb + sta + TILE_BYTES + (wm + 16 * i) * 48 + aoff);
            #pragma unroll
            for (int j = 0; j < 4; j++) mma16816(acc[i][j], al, bh + 2 * j, acc[i][j]);
        }

        if (kc + 1 < NC) {
            const int nsta = ((st ^ 1) << 1) * TILE_BYTES;
            uint2 h, l;
            split4(a0, h, l);
            *(uint2*)(sm + nsta + soff) = h;
            *(uint2*)(sm + nsta + TILE_BYTES + soff) = l;
            split4(a1, h, l);
            *(uint2*)(sm + nsta + soff + 64 * 48) = h;
            *(uint2*)(sm + nsta + TILE_BYTES + soff + 64 * 48) = l;
            split4(b0, h, l);
            *(uint2*)(sm + BOFF + nsta + soff) = h;
            *(uint2*)(sm + BOFF + nsta + TILE_BYTES + soff) = l;
            split4(b1, h, l);
            *(uint2*)(sm + BOFF + nsta + soff + 64 * 48) = h;
            *(uint2*)(sm + BOFF + nsta + TILE_BYTES + soff + 64 * 48) = l;
        }
        __syncthreads();
    }

    // epilogue
    const int g = lane >> 2, t2 = (lane & 3) << 1;
    #pragma unroll
    for (int j = 0; j < 4; j++) {
        const int col = n0 + wn + 8 * j + t2;
        const float bx = bias[col], by = bias[col + 1];
        #pragma unroll
        for (int i = 0; i < 4; i++) {
            const int row = m0 + wm + 16 * i + g;
            float v0 = acc[i][j][0] + bx, v1 = acc[i][j][1] + by;
            float v2 = acc[i][j][2] + bx, v3 = acc[i][j][3] + by;
            if (RELU) {
                v0 = fmaxf(v0, 0.f); v1 = fmaxf(v1, 0.f);
                v2 = fmaxf(v2, 0.f); v3 = fmaxf(v3, 0.f);
            }
            if (RES) {
                float2 r0 = *(const float2*)(res + (size_t)row * N + col);
                float2 r1 = *(const float2*)(res + (size_t)(row + 8) * N + col);
                v0 += r0.x; v1 += r0.y; v2 += r1.x; v3 += r1.y;
            }
            if (OBF16) {
                __nv_bfloat16* Cb = (__nv_bfloat16*)Cout;
                *(uint32_t*)(Cb + (size_t)row * N + col)       = pack_bf16(v0, v1);
                *(uint32_t*)(Cb + (size_t)(row + 8) * N + col) = pack_bf16(v2, v3);
            } else {
                float* Cf = (float*)Cout;
                *(float2*)(Cf + (size_t)row * N + col)       = make_float2(v0, v1);
                *(float2*)(Cf + (size_t)(row + 8) * N + col) = make_float2(v2, v3);
            }
        }
    }
}

// ====================== HMMA flash attention ==============================
// q-tile 128 x head, 8 warps (warp = 16 q rows), K/V chunks of 64 keys.
__global__ __launch_bounds__(256, 2) void flash(const __nv_bfloat16* __restrict__ Q,
                                                const __nv_bfloat16* __restrict__ K,
                                                const __nv_bfloat16* __restrict__ V,
                                                float* __restrict__ O) {
    __shared__ __align__(16) __nv_bfloat16 Qs[128 * 72];
    __shared__ __align__(16) __nv_bfloat16 Ks[64 * 72];
    __shared__ __align__(16) __nv_bfloat16 Vs[64 * 72];
    const int tid = threadIdx.x, lane = tid & 31, wid = tid >> 5;
    const int q0 = blockIdx.x << 7;
    const int hc = blockIdx.y << 6;
    const uint32_t sQ = smem_u32(Qs), sK = smem_u32(Ks), sV = smem_u32(Vs);

    #pragma unroll
    for (int j = 0; j < 4; j++) {
        int idx = tid + 256 * j;
        int r = idx >> 3, c8 = (idx & 7) << 3;
        *(uint4*)(Qs + r * 72 + c8) =
            *(const uint4*)(Q + (size_t)(q0 + r) * HID + hc + c8);
    }
    __syncthreads();

    uint32_t qf[4][4];
    {
        uint32_t ab = sQ + (wid * 16 + (lane & 15)) * 144 + (lane >> 4) * 16;
        #pragma unroll
        for (int c = 0; c < 4; c++) ldsm4(qf[c], ab + c * 32);
    }

    const uint32_t kboff = ((lane & 7) + ((lane >> 4) << 3)) * 144 + ((lane & 8) << 1);
    const uint32_t vboff = ((lane & 7) + (lane & 8)) * 144 + (lane >> 4) * 16;

    float o[8][4] = {};
    float m0r = -1e30f, m1r = -1e30f, l0 = 0.f, l1 = 0.f;

    for (int kt = 0; kt < SEQ; kt += 64) {
        __syncthreads();
        #pragma unroll
        for (int j = 0; j < 2; j++) {
            int idx = tid + 256 * j;
            int r = idx >> 3, c8 = (idx & 7) << 3;
            *(uint4*)(Ks + r * 72 + c8) =
                *(const uint4*)(K + (size_t)(kt + r) * HID + hc + c8);
            *(uint4*)(Vs + r * 72 + c8) =
                *(const uint4*)(V + (size_t)(kt + r) * HID + hc + c8);
        }
        __syncthreads();

        // S = Q @ K^T  (fp32 accum)
        float s[8][4];
        #pragma unroll
        for (int j = 0; j < 8; j++)
            #pragma unroll
            for (int e = 0; e < 4; e++) s[j][e] = 0.f;
        #pragma unroll
        for (int c = 0; c < 4; c++) {
            uint32_t kb[16];
            #pragma unroll
            for (int h = 0; h < 4; h++)
                ldsm4(kb + 4 * h, sK + h * 2304 + kboff + 32 * c);
            #pragma unroll
            for (int j = 0; j < 8; j++) mma16816(s[j], qf[c], kb + 2 * j, s[j]);
        }

        // online softmax (rows g and g+8; quad t-lanes hold full row)
        float rm0 = -1e30f, rm1 = -1e30f;
        #pragma unroll
        for (int j = 0; j < 8; j++) {
            s[j][0] *= 0.125f; s[j][1] *= 0.125f;
            s[j][2] *= 0.125f; s[j][3] *= 0.125f;
            rm0 = fmaxf(rm0, fmaxf(s[j][0], s[j][1]));
            rm1 = fmaxf(rm1, fmaxf(s[j][2], s[j][3]));
        }
        rm0 = fmaxf(rm0, __shfl_xor_sync(0xffffffffu, rm0, 1));
        rm0 = fmaxf(rm0, __shfl_xor_sync(0xffffffffu, rm0, 2));
        rm1 = fmaxf(rm1, __shfl_xor_sync(0xffffffffu, rm1, 1));
        rm1 = fmaxf(rm1, __shfl_xor_sync(0xffffffffu, rm1, 2));
        float mn0 = fmaxf(m0r, rm0), mn1 = fmaxf(m1r, rm1);
        float al0 = __expf(m0r - mn0), al1 = __expf(m1r - mn1);
        m0r = mn0; m1r = mn1;
        float rs0 = 0.f, rs1 = 0.f;
        #pragma unroll
        for (int j = 0; j < 8; j++) {
            s[j][0] = __expf(s[j][0] - mn0); rs0 += s[j][0];
            s[j][1] = __expf(s[j][1] - mn0); rs0 += s[j][1];
            s[j][2] = __expf(s[j][2] - mn1); rs1 += s[j][2];
            s[j][3] = __expf(s[j][3] - mn1); rs1 += s[j][3];
        }
        rs0 += __shfl_xor_sync(0xffffffffu, rs0, 1);
        rs0 += __shfl_xor_sync(0xffffffffu, rs0, 2);
        rs1 += __shfl_xor_sync(0xffffffffu, rs1, 1);
        rs1 += __shfl_xor_sync(0xffffffffu, rs1, 2);
        l0 = l0 * al0 + rs0;
        l1 = l1 * al1 + rs1;
        #pragma unroll
        for (int j = 0; j < 8; j++) {
            o[j][0] *= al0; o[j][1] *= al0;
            o[j][2] *= al1; o[j][3] *= al1;
        }

        // P (bf16 a-frags) @ V
        uint32_t pa[4][4];
        #pragma unroll
        for (int c = 0; c < 4; c++) {
            pa[c][0] = pack_bf16(s[2 * c][0],     s[2 * c][1]);
            pa[c][1] = pack_bf16(s[2 * c][2],     s[2 * c][3]);
            pa[c][2] = pack_bf16(s[2 * c + 1][0], s[2 * c + 1][1]);
            pa[c][3] = pack_bf16(s[2 * c + 1][2], s[2 * c + 1][3]);
        }
        #pragma unroll
        for (int c = 0; c < 4; c++) {
            uint32_t vb[16];
            #pragma unroll
            for (int h = 0; h < 4; h++)
                ldsm4t(vb + 4 * h, sV + c * 2304 + vboff + 32 * h);
            #pragma unroll
            for (int j = 0; j < 8; j++) mma16816(o[j], pa[c], vb + 2 * j, o[j]);
        }
    }

    const float inv0 = 1.0f / l0, inv1 = 1.0f / l1;
    #pragma unroll
    for (int j = 0; j < 8; j++) {
        int row = q0 + wid * 16 + (lane >> 2);
        int col = hc + 8 * j + ((lane & 3) << 1);
        *(float2*)(O + (size_t)row * HID + col) =
            make_float2(o[j][0] * inv0, o[j][1] * inv0);
        *(float2*)(O + (size_t)(row + 8) * HID + col) =
            make_float2(o[j][2] * inv1, o[j][3] * inv1);
    }
}

// ---------------- launch --------------------------------------------------
extern "C" void kernel_launch(void* const* d_in, const int* in_sizes, int n_in,
                              void* d_out, int out_size) {
    const float* x     = (const float*)d_in[0];
    const float* an_w  = (const float*)d_in[1];
    const float* an_b  = (const float*)d_in[2];
    const float* q_w   = (const float*)d_in[3];
    const float* q_b   = (const float*)d_in[4];
    const float* k_w   = (const float*)d_in[5];
    const float* k_b   = (const float*)d_in[6];
    const float* v_w   = (const float*)d_in[7];
    const float* v_b   = (const float*)d_in[8];
    const float* o_w   = (const float*)d_in[9];
    const float* o_b   = (const float*)d_in[10];
    const float* fn_w  = (const float*)d_in[11];
    const float* fn_b  = (const float*)d_in[12];
    const float* ff1_w = (const float*)d_in[13];
    const float* ff1_b = (const float*)d_in[14];
    const float* ff2_w = (const float*)d_in[15];
    const float* ff2_b = (const float*)d_in[16];
    float* out = (float*)d_out;

    float *xn, *ctx, *x1, *hbuf;
    __nv_bfloat16 *qb, *kb, *vb;
    cudaGetSymbolAddress((void**)&xn,   g_xn);
    cudaGetSymbolAddress((void**)&qb,   g_qb);
    cudaGetSymbolAddress((void**)&kb,   g_kb);
    cudaGetSymbolAddress((void**)&vb,   g_vb);
    cudaGetSymbolAddress((void**)&ctx,  g_ctx);
    cudaGetSymbolAddress((void**)&x1,   g_x1);
    cudaGetSymbolAddress((void**)&hbuf, g_h);

    cudaFuncSetAttribute(hgemm<0, 0, 1>, cudaFuncAttributeMaxDynamicSharedMemorySize, GSMEM);
    cudaFuncSetAttribute(hgemm<0, 0, 0>, cudaFuncAttributeMaxDynamicSharedMemorySize, GSMEM);
    cudaFuncSetAttribute(hgemm<1, 0, 0>, cudaFuncAttributeMaxDynamicSharedMemorySize, GSMEM);
    cudaFuncSetAttribute(hgemm<0, 1, 0>, cudaFuncAttributeMaxDynamicSharedMemorySize, GSMEM);

    dim3 g_proj(HID / 128, SEQ / 128);     // (8, 32)
    dim3 g_ff1 (INTER / 128, SEQ / 128);   // (32, 32)

    ln_kernel<<<SEQ, 256>>>(x, an_w, an_b, xn);
    hgemm<0, 0, 1><<<g_proj, 256, GSMEM>>>(xn, q_w, q_b, nullptr, qb, SEQ, HID, HID);
    hgemm<0, 0, 1><<<g_proj, 256, GSMEM>>>(xn, k_w, k_b, nullptr, kb, SEQ, HID, HID);
    hgemm<0, 0, 1><<<g_proj, 256, GSMEM>>>(xn, v_w, v_b, nullptr, vb, SEQ, HID, HID);
    flash<<<dim3(SEQ / 128, NH), 256>>>(qb, kb, vb, ctx);
    hgemm<0, 1, 0><<<g_proj, 256, GSMEM>>>(ctx, o_w, o_b, x, x1, SEQ, HID, HID);
    ln_kernel<<<SEQ, 256>>>(x1, fn_w, fn_b, xn);
    hgemm<1, 0, 0><<<g_ff1, 256, GSMEM>>>(xn, ff1_w, ff1_b, nullptr, hbuf, SEQ, INTER, HID);
    hgemm<0, 1, 0><<<g_proj, 256, GSMEM>>>(hbuf, ff2_w, ff2_b, x1, out, SEQ, HID, INTER);
}